// round 17
// baseline (speedup 1.0000x reference)
#include <cuda_runtime.h>

// Fused maxpool-argmax + sigma gather — granularity sweep, step 4.
//
// Measured CTA-granularity gradient (all else identical):
//   grid 1024 -> 28.29us, 2048 -> 26.88us, 4096 -> 26.24us (5415 GB/s).
// Mechanism: finer CTAs let work-stealing smooth per-SM/L2-die spread.
// This round: grid 8192 (4 rows/chunk). Pool prologue now runs 8192x but mu
// is fully L2-resident (512KB; 32MB of L2 reads vs L2 at 42% util) and the
// ALU cost is negligible vs the gather body.
//
// Grid: 128 bc * 64 chunks = 8192 blocks, 256 threads.
__global__ __launch_bounds__(256, 8)
void fused_pool_gather_kernel(const float* __restrict__ mu,
                              const float* __restrict__ sigma,
                              float* __restrict__ out_mu,
                              float* __restrict__ out_sig) {
    __shared__ int scol[256];

    const int bc    = blockIdx.x >> 6;    // 0..127
    const int chunk = blockIdx.x & 63;    // 0..63 (4 output rows each)
    const int tid   = threadIdx.x;        // output column j

    // ---- pool/argmax for window `tid` (mu: 4KB/bc, L2-resident) ----
    {
        const int ho = tid >> 4;
        const int wo = tid & 15;
        const float* base = mu + (size_t)bc * 1024;
        const int r0 = 2 * ho;
        const int c0 = 2 * wo;

        const float v0 = base[r0 * 32 + c0];
        const float v1 = base[r0 * 32 + c0 + 1];
        const float v2 = base[(r0 + 1) * 32 + c0];
        const float v3 = base[(r0 + 1) * 32 + c0 + 1];

        float m = v0; int k = 0;
        if (v1 > m) { m = v1; k = 1; }    // strict >: first-max (jnp.argmax)
        if (v2 > m) { m = v2; k = 2; }
        if (v3 > m) { m = v3; k = 3; }

        scol[tid] = (r0 + (k >> 1)) * 32 + (c0 + (k & 1));
        if (chunk == 0) out_mu[bc * 256 + tid] = m;
    }
    __syncthreads();

    // ---- gather: out[i][tid] = sigma[bc][scol[i]][scol[tid]] ----
    const int    cj = scol[tid];
    const float* sb = sigma   + ((size_t)bc << 20);
    float*       ob = out_sig + (size_t)bc * 65536 + tid;
    const int    i0 = chunk * 4;

    int r[4];
    #pragma unroll
    for (int t = 0; t < 4; ++t)            // index prefetch (broadcast LDS)
        r[t] = scol[i0 + t];

    float v[4];
    #pragma unroll
    for (int t = 0; t < 4; ++t)            // 4 independent scattered LDGs
        v[t] = __ldcs(sb + ((size_t)r[t] << 10) + cj);

    #pragma unroll
    for (int t = 0; t < 4; ++t)            // 4 coalesced plain STG.32
        ob[(size_t)(i0 + t) * 256] = v[t];
}

extern "C" void kernel_launch(void* const* d_in, const int* in_sizes, int n_in,
                              void* d_out, int out_size) {
    const float* mu    = (const float*)d_in[0];
    const float* sigma = (const float*)d_in[1];
    if (n_in >= 2 && in_sizes[0] > in_sizes[1]) {
        sigma = (const float*)d_in[0];
        mu    = (const float*)d_in[1];
    }

    float* out_mu  = (float*)d_out;            // 32768 elements
    float* out_sig = out_mu + 32768;           // 8388608 elements

    fused_pool_gather_kernel<<<8192, 256>>>(mu, sigma, out_mu, out_sig);
}